// round 4
// baseline (speedup 1.0000x reference)
#include <cuda_runtime.h>

// ScorePredictor: 3x DistMult edge scoring, DRAM-traffic-optimized.
// score[e] = clip( sum_d head[src[e],d] * rel[d] * tail[dst[e],d], 0, 1 )
//
// Inputs (metadata order):
//   0: x_drug    [N_DRUG * D] f32   (N_DRUG=10000, D=2048, 80 MB)
//   1: x_protein [N_PROT * D] f32   (N_PROT=20000, 160 MB)
//   2: rel_ddi [D]  3: rel_dpi [D]
//   4: ddi_src [E]  5: ddi_dst [E]
//   6: dpi_src [E]  7: dpi_dst [E]
//   8: ppi_src [E]  9: ppi_dst [E]
// Output: [3E] f32 = concat(score_ddi, score_dpi, score_ppi)
//
// Strategy: x_drug (80 MB) fits in GB300's ~126 MB L2. Pin it with
// L2::evict_last (sm_103 ptxas requires 256-bit vectors for the hint) during
// the ddi and dpi phases. Three sequential kernels = hard phase boundaries.

#define D_DIM 2048
#define WARPS_PER_BLOCK 8
#define THREADS_PER_BLOCK (WARPS_PER_BLOCK * 32)

struct f8 { float v[8]; };

// 256-bit global load, non-coherent, L2 evict_last (pin in L2)
__device__ __forceinline__ f8 ldg_f8_pin(const float* p) {
    unsigned r0, r1, r2, r3, r4, r5, r6, r7;
    asm volatile(
        "ld.global.nc.L2::evict_last.v8.b32 {%0,%1,%2,%3,%4,%5,%6,%7}, [%8];"
        : "=r"(r0), "=r"(r1), "=r"(r2), "=r"(r3),
          "=r"(r4), "=r"(r5), "=r"(r6), "=r"(r7)
        : "l"(p));
    f8 o;
    o.v[0] = __uint_as_float(r0); o.v[1] = __uint_as_float(r1);
    o.v[2] = __uint_as_float(r2); o.v[3] = __uint_as_float(r3);
    o.v[4] = __uint_as_float(r4); o.v[5] = __uint_as_float(r5);
    o.v[6] = __uint_as_float(r6); o.v[7] = __uint_as_float(r7);
    return o;
}

// 256-bit global load, non-coherent, default L2 policy
__device__ __forceinline__ f8 ldg_f8(const float* p) {
    unsigned r0, r1, r2, r3, r4, r5, r6, r7;
    asm volatile(
        "ld.global.nc.v8.b32 {%0,%1,%2,%3,%4,%5,%6,%7}, [%8];"
        : "=r"(r0), "=r"(r1), "=r"(r2), "=r"(r3),
          "=r"(r4), "=r"(r5), "=r"(r6), "=r"(r7)
        : "l"(p));
    f8 o;
    o.v[0] = __uint_as_float(r0); o.v[1] = __uint_as_float(r1);
    o.v[2] = __uint_as_float(r2); o.v[3] = __uint_as_float(r3);
    o.v[4] = __uint_as_float(r4); o.v[5] = __uint_as_float(r5);
    o.v[6] = __uint_as_float(r6); o.v[7] = __uint_as_float(r7);
    return o;
}

template <bool PIN_HEAD, bool PIN_TAIL>
__global__ __launch_bounds__(THREADS_PER_BLOCK)
void edge_score_phase(
    const float* __restrict__ x_head,
    const float* __restrict__ x_tail,
    const float* __restrict__ rel,
    const int*   __restrict__ src,
    const int*   __restrict__ dst,
    float*       __restrict__ out,
    int E)
{
    const int warp = threadIdx.x >> 5;
    const int lane = threadIdx.x & 31;
    const int eid  = blockIdx.x * WARPS_PER_BLOCK + warp;
    if (eid >= E) return;

    const float* head = x_head + (size_t)__ldg(src + eid) * D_DIM;
    const float* tail = x_tail + (size_t)__ldg(dst + eid) * D_DIM;

    float acc = 0.0f;

    // 2048 dims / warp: each lane handles 8 chunks of 8 floats (256-bit loads).
    #pragma unroll
    for (int k = 0; k < D_DIM / (32 * 8); ++k) {
        const int idx = (k * 32 + lane) * 8;
        f8 h = PIN_HEAD ? ldg_f8_pin(head + idx) : ldg_f8(head + idx);
        f8 t = PIN_TAIL ? ldg_f8_pin(tail + idx) : ldg_f8(tail + idx);
        float4 r0 = __ldg(reinterpret_cast<const float4*>(rel + idx));
        float4 r1 = __ldg(reinterpret_cast<const float4*>(rel + idx + 4));
        acc = fmaf(h.v[0] * r0.x, t.v[0], acc);
        acc = fmaf(h.v[1] * r0.y, t.v[1], acc);
        acc = fmaf(h.v[2] * r0.z, t.v[2], acc);
        acc = fmaf(h.v[3] * r0.w, t.v[3], acc);
        acc = fmaf(h.v[4] * r1.x, t.v[4], acc);
        acc = fmaf(h.v[5] * r1.y, t.v[5], acc);
        acc = fmaf(h.v[6] * r1.z, t.v[6], acc);
        acc = fmaf(h.v[7] * r1.w, t.v[7], acc);
    }

    #pragma unroll
    for (int off = 16; off > 0; off >>= 1)
        acc += __shfl_xor_sync(0xffffffffu, acc, off);

    if (lane == 0)
        out[eid] = fminf(fmaxf(acc, 0.0f), 1.0f);
}

extern "C" void kernel_launch(void* const* d_in, const int* in_sizes, int n_in,
                              void* d_out, int out_size)
{
    const float* x_drug  = (const float*)d_in[0];
    const float* x_prot  = (const float*)d_in[1];
    const float* rel_ddi = (const float*)d_in[2];
    const float* rel_dpi = (const float*)d_in[3];
    const int*   ddi_src = (const int*)d_in[4];
    const int*   ddi_dst = (const int*)d_in[5];
    const int*   dpi_src = (const int*)d_in[6];
    const int*   dpi_dst = (const int*)d_in[7];
    const int*   ppi_src = (const int*)d_in[8];
    const int*   ppi_dst = (const int*)d_in[9];
    float* out = (float*)d_out;

    const int E = in_sizes[4];  // 100000
    const int blocks = (E + WARPS_PER_BLOCK - 1) / WARPS_PER_BLOCK;

    // Phase 1: ddi — both sides x_drug (80 MB, fits L2). Pin it.
    edge_score_phase<true, true><<<blocks, THREADS_PER_BLOCK>>>(
        x_drug, x_drug, rel_ddi, ddi_src, ddi_dst, out, E);

    // Phase 2: dpi — drug heads pinned (warm from phase 1), protein tails default.
    edge_score_phase<true, false><<<blocks, THREADS_PER_BLOCK>>>(
        x_drug, x_prot, rel_dpi, dpi_src, dpi_dst, out + E, E);

    // Phase 3: ppi — both sides x_protein (160 MB, slightly over L2). Default.
    edge_score_phase<false, false><<<blocks, THREADS_PER_BLOCK>>>(
        x_prot, x_prot, rel_dpi, ppi_src, ppi_dst, out + 2 * E, E);
}